// round 1
// baseline (speedup 1.0000x reference)
#include <cuda_runtime.h>

#define N_NODES 50000
#define N_EDGES 800000
#define IN_F    128
#define HID     128
#define NCLS    47
#define NCLS_PAD 48

// ---------------- scratch (device globals: no allocation allowed) ----------
__device__ int   g_deg_out[N_NODES];
__device__ int   g_deg_in [N_NODES];
__device__ float g_norm_src[N_NODES];
__device__ float g_norm_dst[N_NODES];
__device__ int   g_row_ptr[N_NODES + 1];
__device__ int   g_fill  [N_NODES];
__device__ int   g_col   [N_EDGES];
__device__ float g_h1[N_NODES * HID];       // (X*ns) @ W1
__device__ float g_H [N_NODES * HID];       // relu(agg1*nd + b1)
__device__ float g_h2[N_NODES * NCLS_PAD];  // (H*ns) @ W2 (padded to 48)

// ---------------- f32x2 packed math helpers --------------------------------
__device__ __forceinline__ unsigned long long pack_dup(float x) {
    unsigned long long r;
    unsigned u = __float_as_uint(x);
    asm("mov.b64 %0, {%1, %1};" : "=l"(r) : "r"(u));
    return r;
}
__device__ __forceinline__ float2 unpack_f32x2(unsigned long long p) {
    unsigned lo, hi;
    asm("mov.b64 {%0, %1}, %2;" : "=r"(lo), "=r"(hi) : "l"(p));
    return make_float2(__uint_as_float(lo), __uint_as_float(hi));
}
#define FMA_F32X2(acc, a, b) \
    asm("fma.rn.f32x2 %0, %1, %2, %0;" : "+l"(acc) : "l"(a), "l"(b))

// ---------------- setup kernels --------------------------------------------
__global__ void zero_kernel() {
    int i = blockIdx.x * blockDim.x + threadIdx.x;
    if (i < N_NODES) { g_deg_out[i] = 0; g_deg_in[i] = 0; g_fill[i] = 0; }
}

__global__ void degree_kernel(const int* __restrict__ src, const int* __restrict__ dst) {
    int e = blockIdx.x * blockDim.x + threadIdx.x;
    if (e < N_EDGES) {
        atomicAdd(&g_deg_out[src[e]], 1);
        atomicAdd(&g_deg_in [dst[e]], 1);
    }
}

__global__ void norm_kernel() {
    int i = blockIdx.x * blockDim.x + threadIdx.x;
    if (i < N_NODES) {
        g_norm_src[i] = rsqrtf(fmaxf((float)g_deg_out[i], 1.0f));
        g_norm_dst[i] = rsqrtf(fmaxf((float)g_deg_in [i], 1.0f));
    }
}

// exclusive prefix sum of g_deg_in -> g_row_ptr, single block of 1024
__global__ void scan_kernel() {
    __shared__ int warp_sums[32];
    const int t = threadIdx.x;
    const int lane = t & 31, w = t >> 5;
    int carry = 0;
    if (t == 0) g_row_ptr[0] = 0;
    for (int base = 0; base < N_NODES; base += 1024) {
        int i = base + t;
        int v = (i < N_NODES) ? g_deg_in[i] : 0;
        // warp inclusive scan
        int x = v;
        #pragma unroll
        for (int o = 1; o < 32; o <<= 1) {
            int y = __shfl_up_sync(0xFFFFFFFFu, x, o);
            if (lane >= o) x += y;
        }
        if (lane == 31) warp_sums[w] = x;
        __syncthreads();
        if (t < 32) {
            int s = warp_sums[t];
            #pragma unroll
            for (int o = 1; o < 32; o <<= 1) {
                int y = __shfl_up_sync(0xFFFFFFFFu, s, o);
                if (t >= o) s += y;
            }
            warp_sums[t] = s;
        }
        __syncthreads();
        int incl = x + ((w > 0) ? warp_sums[w - 1] : 0);
        if (i < N_NODES) g_row_ptr[i + 1] = carry + incl;
        carry += warp_sums[31];
        __syncthreads();  // protect warp_sums for next iteration
    }
}

__global__ void scatter_kernel(const int* __restrict__ src, const int* __restrict__ dst) {
    int e = blockIdx.x * blockDim.x + threadIdx.x;
    if (e < N_EDGES) {
        int d = dst[e];
        int pos = atomicAdd(&g_fill[d], 1);
        g_col[g_row_ptr[d] + pos] = src[e];
    }
}

// ---------------- GEMM1: g_h1 = (X * norm_src) @ W1  (M=50000,N=128,K=128) --
// 256 threads, 64-row tile; thread computes 4 rows x 8 cols via f32x2
__global__ void gemm1_kernel(const float* __restrict__ X, const float* __restrict__ W1) {
    extern __shared__ float sm[];
    float* Ws = sm;                  // 128 x 128
    float* Xs = sm + 128 * 128;      // 64 x 132 (padded)
    const int tid = threadIdx.x;
    const int tx = tid & 15, ty = tid >> 4;
    const int row0 = blockIdx.x * 64;

    {   // load W1: 4096 float4 / 256 threads
        const float4* Wg = (const float4*)W1;
        float4* Wsh = (float4*)Ws;
        #pragma unroll
        for (int i = 0; i < 16; i++) Wsh[tid + i * 256] = Wg[tid + i * 256];
    }
    {   // load X tile scaled by norm_src: 2048 float4
        #pragma unroll
        for (int i = 0; i < 8; i++) {
            int idx = tid + i * 256;
            int r = idx >> 5, c = idx & 31;
            int grow = row0 + r;
            float4 v = make_float4(0.f, 0.f, 0.f, 0.f);
            if (grow < N_NODES) {
                v = ((const float4*)X)[grow * 32 + c];
                float ns = g_norm_src[grow];
                v.x *= ns; v.y *= ns; v.z *= ns; v.w *= ns;
            }
            *(float4*)(Xs + r * 132 + c * 4) = v;
        }
    }
    __syncthreads();

    unsigned long long acc[4][4];
    #pragma unroll
    for (int r = 0; r < 4; r++)
        #pragma unroll
        for (int c = 0; c < 4; c++) acc[r][c] = 0ull;

    #pragma unroll 4
    for (int k = 0; k < 128; k++) {
        ulonglong2 b01 = *(const ulonglong2*)(Ws + k * 128 + tx * 8);
        ulonglong2 b23 = *(const ulonglong2*)(Ws + k * 128 + tx * 8 + 4);
        unsigned long long b[4] = {b01.x, b01.y, b23.x, b23.y};
        #pragma unroll
        for (int r = 0; r < 4; r++) {
            unsigned long long a = pack_dup(Xs[(ty * 4 + r) * 132 + k]);
            #pragma unroll
            for (int c = 0; c < 4; c++) FMA_F32X2(acc[r][c], a, b[c]);
        }
    }

    #pragma unroll
    for (int r = 0; r < 4; r++) {
        int grow = row0 + ty * 4 + r;
        if (grow < N_NODES) {
            float2 p0 = unpack_f32x2(acc[r][0]);
            float2 p1 = unpack_f32x2(acc[r][1]);
            float2 p2 = unpack_f32x2(acc[r][2]);
            float2 p3 = unpack_f32x2(acc[r][3]);
            float4* out = (float4*)(g_h1 + grow * 128);
            out[tx * 2]     = make_float4(p0.x, p0.y, p1.x, p1.y);
            out[tx * 2 + 1] = make_float4(p2.x, p2.y, p3.x, p3.y);
        }
    }
}

// ---------------- agg1: g_H = relu(segsum(h1[src]->dst)*nd + b1) ------------
// one warp per dst node, float4 per lane (128 feats)
__global__ void agg1_kernel(const float* __restrict__ b1) {
    int node = (blockIdx.x * blockDim.x + threadIdx.x) >> 5;
    int lane = threadIdx.x & 31;
    if (node >= N_NODES) return;
    int beg = g_row_ptr[node], end = g_row_ptr[node + 1];
    const float4* h4 = (const float4*)g_h1;
    float4 acc = make_float4(0.f, 0.f, 0.f, 0.f);
    int e = beg;
    for (; e + 4 <= end; e += 4) {
        int s0 = g_col[e], s1 = g_col[e + 1], s2 = g_col[e + 2], s3 = g_col[e + 3];
        float4 v0 = h4[s0 * 32 + lane];
        float4 v1 = h4[s1 * 32 + lane];
        float4 v2 = h4[s2 * 32 + lane];
        float4 v3 = h4[s3 * 32 + lane];
        acc.x += (v0.x + v1.x) + (v2.x + v3.x);
        acc.y += (v0.y + v1.y) + (v2.y + v3.y);
        acc.z += (v0.z + v1.z) + (v2.z + v3.z);
        acc.w += (v0.w + v1.w) + (v2.w + v3.w);
    }
    for (; e < end; e++) {
        int s = g_col[e];
        float4 v = h4[s * 32 + lane];
        acc.x += v.x; acc.y += v.y; acc.z += v.z; acc.w += v.w;
    }
    float nd = g_norm_dst[node];
    float4 bb = ((const float4*)b1)[lane];
    float4 r;
    r.x = fmaxf(fmaf(acc.x, nd, bb.x), 0.f);
    r.y = fmaxf(fmaf(acc.y, nd, bb.y), 0.f);
    r.z = fmaxf(fmaf(acc.z, nd, bb.z), 0.f);
    r.w = fmaxf(fmaf(acc.w, nd, bb.w), 0.f);
    ((float4*)g_H)[node * 32 + lane] = r;
}

// ---------------- GEMM2: g_h2 = (g_H * norm_src) @ W2 (N=47 padded 48) ------
// 192 threads (16x12), 64-row tile; thread: 4 rows x 4 cols via f32x2
__global__ void gemm2_kernel(const float* __restrict__ W2) {
    extern __shared__ float sm[];
    float* Ws = sm;                 // 128 x 48
    float* Xs = sm + 128 * 48;      // 64 x 132
    const int tid = threadIdx.x;
    const int tx = tid % 12, ty = tid / 12;
    const int row0 = blockIdx.x * 64;

    for (int i = tid; i < 128 * 48; i += 192) {
        int k = i / 48, c = i % 48;
        Ws[i] = (c < NCLS) ? W2[k * NCLS + c] : 0.0f;
    }
    for (int i = tid; i < 64 * 32; i += 192) {
        int r = i >> 5, c = i & 31;
        int grow = row0 + r;
        float4 v = make_float4(0.f, 0.f, 0.f, 0.f);
        if (grow < N_NODES) {
            v = ((const float4*)g_H)[grow * 32 + c];
            float ns = g_norm_src[grow];
            v.x *= ns; v.y *= ns; v.z *= ns; v.w *= ns;
        }
        *(float4*)(Xs + r * 132 + c * 4) = v;
    }
    __syncthreads();

    unsigned long long acc[4][2];
    #pragma unroll
    for (int r = 0; r < 4; r++) { acc[r][0] = 0ull; acc[r][1] = 0ull; }

    #pragma unroll 4
    for (int k = 0; k < 128; k++) {
        ulonglong2 bp = *(const ulonglong2*)(Ws + k * 48 + tx * 4);
        #pragma unroll
        for (int r = 0; r < 4; r++) {
            unsigned long long a = pack_dup(Xs[(ty * 4 + r) * 132 + k]);
            FMA_F32X2(acc[r][0], a, bp.x);
            FMA_F32X2(acc[r][1], a, bp.y);
        }
    }
    #pragma unroll
    for (int r = 0; r < 4; r++) {
        int grow = row0 + ty * 4 + r;
        if (grow < N_NODES) {
            float2 p0 = unpack_f32x2(acc[r][0]);
            float2 p1 = unpack_f32x2(acc[r][1]);
            *(float4*)(g_h2 + grow * NCLS_PAD + tx * 4) =
                make_float4(p0.x, p0.y, p1.x, p1.y);
        }
    }
}

// ---------------- agg2: out = segsum(h2[src]->dst)*nd + b2 (47 feats) -------
__global__ void agg2_kernel(const float* __restrict__ b2, float* __restrict__ out) {
    int node = (blockIdx.x * blockDim.x + threadIdx.x) >> 5;
    int lane = threadIdx.x & 31;
    if (node >= N_NODES) return;
    int beg = g_row_ptr[node], end = g_row_ptr[node + 1];
    bool hi = lane < (NCLS - 32);   // lane+32 < 47
    float a0 = 0.f, a1 = 0.f;
    int e = beg;
    for (; e + 2 <= end; e += 2) {
        int s0 = g_col[e], s1 = g_col[e + 1];
        const float* r0 = g_h2 + s0 * NCLS_PAD;
        const float* r1 = g_h2 + s1 * NCLS_PAD;
        float u0 = r0[lane], u1 = r1[lane];
        float w0 = hi ? r0[lane + 32] : 0.f;
        float w1 = hi ? r1[lane + 32] : 0.f;
        a0 += u0 + u1;
        a1 += w0 + w1;
    }
    for (; e < end; e++) {
        int s = g_col[e];
        const float* r0 = g_h2 + s * NCLS_PAD;
        a0 += r0[lane];
        if (hi) a1 += r0[lane + 32];
    }
    float nd = g_norm_dst[node];
    out[node * NCLS + lane] = fmaf(a0, nd, b2[lane]);
    if (hi) out[node * NCLS + lane + 32] = fmaf(a1, nd, b2[lane + 32]);
}

// ---------------- launch ----------------------------------------------------
extern "C" void kernel_launch(void* const* d_in, const int* in_sizes, int n_in,
                              void* d_out, int out_size) {
    const float* X  = (const float*)d_in[0];
    const int*   ei = (const int*)  d_in[1];
    const float* W1 = (const float*)d_in[2];
    const float* b1 = (const float*)d_in[3];
    const float* W2 = (const float*)d_in[4];
    const float* b2 = (const float*)d_in[5];
    const int* src = ei;
    const int* dst = ei + N_EDGES;
    float* out = (float*)d_out;

    const int SMEM1 = (128 * 128 + 64 * 132) * (int)sizeof(float);  // 99328
    const int SMEM2 = (128 * 48  + 64 * 132) * (int)sizeof(float);  // 58368
    cudaFuncSetAttribute(gemm1_kernel, cudaFuncAttributeMaxDynamicSharedMemorySize, SMEM1);
    cudaFuncSetAttribute(gemm2_kernel, cudaFuncAttributeMaxDynamicSharedMemorySize, SMEM2);

    zero_kernel   <<<(N_NODES + 255) / 256, 256>>>();
    degree_kernel <<<(N_EDGES + 255) / 256, 256>>>(src, dst);
    norm_kernel   <<<(N_NODES + 255) / 256, 256>>>();
    scan_kernel   <<<1, 1024>>>();
    scatter_kernel<<<(N_EDGES + 255) / 256, 256>>>(src, dst);

    gemm1_kernel  <<<(N_NODES + 63) / 64, 256, SMEM1>>>(X, W1);
    agg1_kernel   <<<(N_NODES + 7) / 8, 256>>>(b1);
    gemm2_kernel  <<<(N_NODES + 63) / 64, 192, SMEM2>>>(W2);
    agg2_kernel   <<<(N_NODES + 7) / 8, 256>>>(b2, out);
}

// round 2
// speedup vs baseline: 1.2217x; 1.2217x over previous
#include <cuda_runtime.h>

#define N_NODES 50000
#define N_EDGES 800000
#define IN_F    128
#define HID     128
#define NCLS    47
#define NCLS_PAD 48

#define SCAN_CHUNK 1024
#define N_CHUNKS ((N_NODES + SCAN_CHUNK - 1) / SCAN_CHUNK)   // 49

// ---------------- scratch (device globals: no allocation allowed) ----------
__device__ int   g_deg_out[N_NODES];
__device__ int   g_deg_in [N_NODES];
__device__ float g_norm_src[N_NODES];
__device__ float g_norm_dst[N_NODES];
__device__ int   g_row_ptr[N_NODES + 1];
__device__ int   g_fill  [N_NODES];
__device__ int   g_col   [N_EDGES];
__device__ int   g_chunk_sum[N_CHUNKS];
__device__ float g_h1[N_NODES * HID];       // (X*ns) @ W1
__device__ float g_H [N_NODES * HID];       // relu(agg1*nd + b1)
__device__ float g_h2[N_NODES * NCLS_PAD];  // (H*ns) @ W2 (padded to 48)

// ---------------- f32x2 packed math helpers --------------------------------
__device__ __forceinline__ unsigned long long pack_dup(float x) {
    unsigned long long r;
    unsigned u = __float_as_uint(x);
    asm("mov.b64 %0, {%1, %1};" : "=l"(r) : "r"(u));
    return r;
}
__device__ __forceinline__ float2 unpack_f32x2(unsigned long long p) {
    unsigned lo, hi;
    asm("mov.b64 {%0, %1}, %2;" : "=r"(lo), "=r"(hi) : "l"(p));
    return make_float2(__uint_as_float(lo), __uint_as_float(hi));
}
#define FMA_F32X2(acc, a, b) \
    asm("fma.rn.f32x2 %0, %1, %2, %0;" : "+l"(acc) : "l"(a), "l"(b))

// ---------------- setup kernels --------------------------------------------
__global__ void zero_kernel() {
    int i = blockIdx.x * blockDim.x + threadIdx.x;
    if (i < N_NODES) { g_deg_out[i] = 0; g_deg_in[i] = 0; g_fill[i] = 0; }
}

__global__ void degree_kernel(const int* __restrict__ src, const int* __restrict__ dst) {
    int e = blockIdx.x * blockDim.x + threadIdx.x;
    if (e < N_EDGES) {
        atomicAdd(&g_deg_out[src[e]], 1);
        atomicAdd(&g_deg_in [dst[e]], 1);
    }
}

__global__ void norm_kernel() {
    int i = blockIdx.x * blockDim.x + threadIdx.x;
    if (i < N_NODES) {
        g_norm_src[i] = rsqrtf(fmaxf((float)g_deg_out[i], 1.0f));
        g_norm_dst[i] = rsqrtf(fmaxf((float)g_deg_in [i], 1.0f));
    }
}

// ---- 3-phase scan: row_ptr = exclusive-prefix-sum(deg_in) -----------------
// phase 1: per-chunk inclusive scan (49 blocks x 1024 thr), chunk totals out
__global__ void scan1_kernel() {
    __shared__ int warp_sums[32];
    const int b = blockIdx.x, t = threadIdx.x;
    const int lane = t & 31, w = t >> 5;
    const int i = b * SCAN_CHUNK + t;
    int v = (i < N_NODES) ? g_deg_in[i] : 0;
    int x = v;
    #pragma unroll
    for (int o = 1; o < 32; o <<= 1) {
        int y = __shfl_up_sync(0xFFFFFFFFu, x, o);
        if (lane >= o) x += y;
    }
    if (lane == 31) warp_sums[w] = x;
    __syncthreads();
    if (t < 32) {
        int s = warp_sums[t];
        #pragma unroll
        for (int o = 1; o < 32; o <<= 1) {
            int y = __shfl_up_sync(0xFFFFFFFFu, s, o);
            if (t >= o) s += y;
        }
        warp_sums[t] = s;
    }
    __syncthreads();
    int incl = x + ((w > 0) ? warp_sums[w - 1] : 0);
    if (i < N_NODES) g_row_ptr[i + 1] = incl;       // chunk-local inclusive
    if (t == SCAN_CHUNK - 1) g_chunk_sum[b] = incl; // chunk total
    if (b == 0 && t == 0) g_row_ptr[0] = 0;
}

// phase 2: one warp, exclusive scan of the 49 chunk totals in place
__global__ void scan2_kernel() {
    const int lane = threadIdx.x;
    int carry = 0;
    for (int base = 0; base < N_CHUNKS; base += 32) {
        int idx = base + lane;
        int v = (idx < N_CHUNKS) ? g_chunk_sum[idx] : 0;
        int x = v;
        #pragma unroll
        for (int o = 1; o < 32; o <<= 1) {
            int y = __shfl_up_sync(0xFFFFFFFFu, x, o);
            if (lane >= o) x += y;
        }
        if (idx < N_CHUNKS) g_chunk_sum[idx] = carry + x - v;  // exclusive
        carry += __shfl_sync(0xFFFFFFFFu, x, 31);
    }
}

// phase 3: add chunk offsets
__global__ void scan3_kernel() {
    int i = blockIdx.x * blockDim.x + threadIdx.x;
    if (i < N_NODES) g_row_ptr[i + 1] += g_chunk_sum[i / SCAN_CHUNK];
}

__global__ void scatter_kernel(const int* __restrict__ src, const int* __restrict__ dst) {
    int e = blockIdx.x * blockDim.x + threadIdx.x;
    if (e < N_EDGES) {
        int d = dst[e];
        int pos = atomicAdd(&g_fill[d], 1);
        g_col[g_row_ptr[d] + pos] = src[e];
    }
}

// ---------------- GEMM1: g_h1 = (X * norm_src) @ W1  (M=50000,N=128,K=128) --
// 256 threads, 128-row tile; thread computes 8 rows x 8 cols via f32x2
__global__ void gemm1_kernel(const float* __restrict__ X, const float* __restrict__ W1) {
    extern __shared__ float sm[];
    float* Ws = sm;                  // 128 x 128
    float* Xs = sm + 128 * 128;      // 128 x 132 (padded)
    const int tid = threadIdx.x;
    const int tx = tid & 15, ty = tid >> 4;   // tx: 16 col groups, ty: 16 row groups
    const int row0 = blockIdx.x * 128;

    {   // load W1: 4096 float4 / 256 threads
        const float4* Wg = (const float4*)W1;
        float4* Wsh = (float4*)Ws;
        #pragma unroll
        for (int i = 0; i < 16; i++) Wsh[tid + i * 256] = Wg[tid + i * 256];
    }
    {   // load X tile scaled by norm_src: 4096 float4
        #pragma unroll
        for (int i = 0; i < 16; i++) {
            int idx = tid + i * 256;
            int r = idx >> 5, c = idx & 31;
            int grow = row0 + r;
            float4 v = make_float4(0.f, 0.f, 0.f, 0.f);
            if (grow < N_NODES) {
                v = ((const float4*)X)[grow * 32 + c];
                float ns = g_norm_src[grow];
                v.x *= ns; v.y *= ns; v.z *= ns; v.w *= ns;
            }
            *(float4*)(Xs + r * 132 + c * 4) = v;
        }
    }
    __syncthreads();

    unsigned long long acc[8][4];
    #pragma unroll
    for (int r = 0; r < 8; r++)
        #pragma unroll
        for (int c = 0; c < 4; c++) acc[r][c] = 0ull;

    #pragma unroll 2
    for (int k = 0; k < 128; k++) {
        ulonglong2 b01 = *(const ulonglong2*)(Ws + k * 128 + tx * 8);
        ulonglong2 b23 = *(const ulonglong2*)(Ws + k * 128 + tx * 8 + 4);
        unsigned long long b[4] = {b01.x, b01.y, b23.x, b23.y};
        #pragma unroll
        for (int r = 0; r < 8; r++) {
            unsigned long long a = pack_dup(Xs[(ty * 8 + r) * 132 + k]);
            #pragma unroll
            for (int c = 0; c < 4; c++) FMA_F32X2(acc[r][c], a, b[c]);
        }
    }

    #pragma unroll
    for (int r = 0; r < 8; r++) {
        int grow = row0 + ty * 8 + r;
        if (grow < N_NODES) {
            float2 p0 = unpack_f32x2(acc[r][0]);
            float2 p1 = unpack_f32x2(acc[r][1]);
            float2 p2 = unpack_f32x2(acc[r][2]);
            float2 p3 = unpack_f32x2(acc[r][3]);
            float4* out = (float4*)(g_h1 + grow * 128);
            out[tx * 2]     = make_float4(p0.x, p0.y, p1.x, p1.y);
            out[tx * 2 + 1] = make_float4(p2.x, p2.y, p3.x, p3.y);
        }
    }
}

// ---------------- agg1: g_H = relu(segsum(h1[src]->dst)*nd + b1) ------------
// one warp per dst node, float4 per lane (128 feats)
__global__ void agg1_kernel(const float* __restrict__ b1) {
    int node = (blockIdx.x * blockDim.x + threadIdx.x) >> 5;
    int lane = threadIdx.x & 31;
    if (node >= N_NODES) return;
    int beg = g_row_ptr[node], end = g_row_ptr[node + 1];
    const float4* h4 = (const float4*)g_h1;
    float4 acc = make_float4(0.f, 0.f, 0.f, 0.f);
    int e = beg;
    for (; e + 4 <= end; e += 4) {
        int s0 = g_col[e], s1 = g_col[e + 1], s2 = g_col[e + 2], s3 = g_col[e + 3];
        float4 v0 = h4[s0 * 32 + lane];
        float4 v1 = h4[s1 * 32 + lane];
        float4 v2 = h4[s2 * 32 + lane];
        float4 v3 = h4[s3 * 32 + lane];
        acc.x += (v0.x + v1.x) + (v2.x + v3.x);
        acc.y += (v0.y + v1.y) + (v2.y + v3.y);
        acc.z += (v0.z + v1.z) + (v2.z + v3.z);
        acc.w += (v0.w + v1.w) + (v2.w + v3.w);
    }
    for (; e < end; e++) {
        int s = g_col[e];
        float4 v = h4[s * 32 + lane];
        acc.x += v.x; acc.y += v.y; acc.z += v.z; acc.w += v.w;
    }
    float nd = g_norm_dst[node];
    float4 bb = ((const float4*)b1)[lane];
    float4 r;
    r.x = fmaxf(fmaf(acc.x, nd, bb.x), 0.f);
    r.y = fmaxf(fmaf(acc.y, nd, bb.y), 0.f);
    r.z = fmaxf(fmaf(acc.z, nd, bb.z), 0.f);
    r.w = fmaxf(fmaf(acc.w, nd, bb.w), 0.f);
    ((float4*)g_H)[node * 32 + lane] = r;
}

// ---------------- GEMM2: g_h2 = (g_H * norm_src) @ W2 (N=47 padded 48) ------
// 192 threads (16x12), 64-row tile; thread: 4 rows x 4 cols via f32x2
__global__ void gemm2_kernel(const float* __restrict__ W2) {
    extern __shared__ float sm[];
    float* Ws = sm;                 // 128 x 48
    float* Xs = sm + 128 * 48;      // 64 x 132
    const int tid = threadIdx.x;
    const int tx = tid % 12, ty = tid / 12;
    const int row0 = blockIdx.x * 64;

    for (int i = tid; i < 128 * 48; i += 192) {
        int k = i / 48, c = i % 48;
        Ws[i] = (c < NCLS) ? W2[k * NCLS + c] : 0.0f;
    }
    for (int i = tid; i < 64 * 32; i += 192) {
        int r = i >> 5, c = i & 31;
        int grow = row0 + r;
        float4 v = make_float4(0.f, 0.f, 0.f, 0.f);
        if (grow < N_NODES) {
            v = ((const float4*)g_H)[grow * 32 + c];
            float ns = g_norm_src[grow];
            v.x *= ns; v.y *= ns; v.z *= ns; v.w *= ns;
        }
        *(float4*)(Xs + r * 132 + c * 4) = v;
    }
    __syncthreads();

    unsigned long long acc[4][2];
    #pragma unroll
    for (int r = 0; r < 4; r++) { acc[r][0] = 0ull; acc[r][1] = 0ull; }

    #pragma unroll 4
    for (int k = 0; k < 128; k++) {
        ulonglong2 bp = *(const ulonglong2*)(Ws + k * 48 + tx * 4);
        #pragma unroll
        for (int r = 0; r < 4; r++) {
            unsigned long long a = pack_dup(Xs[(ty * 4 + r) * 132 + k]);
            FMA_F32X2(acc[r][0], a, bp.x);
            FMA_F32X2(acc[r][1], a, bp.y);
        }
    }
    #pragma unroll
    for (int r = 0; r < 4; r++) {
        int grow = row0 + ty * 4 + r;
        if (grow < N_NODES) {
            float2 p0 = unpack_f32x2(acc[r][0]);
            float2 p1 = unpack_f32x2(acc[r][1]);
            *(float4*)(g_h2 + grow * NCLS_PAD + tx * 4) =
                make_float4(p0.x, p0.y, p1.x, p1.y);
        }
    }
}

// ---------------- agg2: out = segsum(h2[src]->dst)*nd + b2 (47 feats) -------
__global__ void agg2_kernel(const float* __restrict__ b2, float* __restrict__ out) {
    int node = (blockIdx.x * blockDim.x + threadIdx.x) >> 5;
    int lane = threadIdx.x & 31;
    if (node >= N_NODES) return;
    int beg = g_row_ptr[node], end = g_row_ptr[node + 1];
    bool hi = lane < (NCLS - 32);   // lane+32 < 47
    float a0 = 0.f, a1 = 0.f;
    int e = beg;
    for (; e + 2 <= end; e += 2) {
        int s0 = g_col[e], s1 = g_col[e + 1];
        const float* r0 = g_h2 + s0 * NCLS_PAD;
        const float* r1 = g_h2 + s1 * NCLS_PAD;
        float u0 = r0[lane], u1 = r1[lane];
        float w0 = hi ? r0[lane + 32] : 0.f;
        float w1 = hi ? r1[lane + 32] : 0.f;
        a0 += u0 + u1;
        a1 += w0 + w1;
    }
    for (; e < end; e++) {
        int s = g_col[e];
        const float* r0 = g_h2 + s * NCLS_PAD;
        a0 += r0[lane];
        if (hi) a1 += r0[lane + 32];
    }
    float nd = g_norm_dst[node];
    out[node * NCLS + lane] = fmaf(a0, nd, b2[lane]);
    if (hi) out[node * NCLS + lane + 32] = fmaf(a1, nd, b2[lane + 32]);
}

// ---------------- launch ----------------------------------------------------
extern "C" void kernel_launch(void* const* d_in, const int* in_sizes, int n_in,
                              void* d_out, int out_size) {
    const float* X  = (const float*)d_in[0];
    const int*   ei = (const int*)  d_in[1];
    const float* W1 = (const float*)d_in[2];
    const float* b1 = (const float*)d_in[3];
    const float* W2 = (const float*)d_in[4];
    const float* b2 = (const float*)d_in[5];
    const int* src = ei;
    const int* dst = ei + N_EDGES;
    float* out = (float*)d_out;

    const int SMEM1 = (128 * 128 + 128 * 132) * (int)sizeof(float);  // 133120
    const int SMEM2 = (128 * 48  + 64 * 132) * (int)sizeof(float);   // 58368
    cudaFuncSetAttribute(gemm1_kernel, cudaFuncAttributeMaxDynamicSharedMemorySize, SMEM1);
    cudaFuncSetAttribute(gemm2_kernel, cudaFuncAttributeMaxDynamicSharedMemorySize, SMEM2);

    zero_kernel   <<<(N_NODES + 255) / 256, 256>>>();
    degree_kernel <<<(N_EDGES + 255) / 256, 256>>>(src, dst);
    norm_kernel   <<<(N_NODES + 255) / 256, 256>>>();
    scan1_kernel  <<<N_CHUNKS, SCAN_CHUNK>>>();
    scan2_kernel  <<<1, 32>>>();
    scan3_kernel  <<<(N_NODES + 255) / 256, 256>>>();
    scatter_kernel<<<(N_EDGES + 255) / 256, 256>>>(src, dst);

    gemm1_kernel  <<<(N_NODES + 127) / 128, 256, SMEM1>>>(X, W1);
    agg1_kernel   <<<(N_NODES + 7) / 8, 256>>>(b1);
    gemm2_kernel  <<<(N_NODES + 63) / 64, 192, SMEM2>>>(W2);
    agg2_kernel   <<<(N_NODES + 7) / 8, 256>>>(b2, out);
}

// round 3
// speedup vs baseline: 1.3089x; 1.0714x over previous
#include <cuda_runtime.h>

#define N_NODES 50000
#define N_EDGES 800000
#define IN_F    128
#define HID     128
#define NCLS    47
#define NCLS_PAD 48

#define SCAN_CHUNK 1024
#define N_CHUNKS ((N_NODES + SCAN_CHUNK - 1) / SCAN_CHUNK)   // 49

// ---------------- scratch (device globals: no allocation allowed) ----------
__device__ int   g_deg_out[N_NODES];
__device__ int   g_deg_in [N_NODES];
__device__ float g_norm_src[N_NODES];
__device__ float g_norm_dst[N_NODES];
__device__ int   g_row_ptr[N_NODES + 1];
__device__ int   g_fill  [N_NODES];
__device__ int   g_col   [N_EDGES];
__device__ int   g_chunk_sum[N_CHUNKS];
__device__ float g_h1[N_NODES * HID];       // X @ W1 (UNscaled)
__device__ float g_H [N_NODES * HID];       // relu(agg1*nd + b1)
__device__ float g_h2[N_NODES * NCLS_PAD];  // (H*ns) @ W2 (padded to 48)

// ---------------- f32x2 packed math helpers --------------------------------
__device__ __forceinline__ unsigned long long pack_dup(float x) {
    unsigned long long r;
    unsigned u = __float_as_uint(x);
    asm("mov.b64 %0, {%1, %1};" : "=l"(r) : "r"(u));
    return r;
}
__device__ __forceinline__ float2 unpack_f32x2(unsigned long long p) {
    unsigned lo, hi;
    asm("mov.b64 {%0, %1}, %2;" : "=r"(lo), "=r"(hi) : "l"(p));
    return make_float2(__uint_as_float(lo), __uint_as_float(hi));
}
#define FMA_F32X2(acc, a, b) \
    asm("fma.rn.f32x2 %0, %1, %2, %0;" : "+l"(acc) : "l"(a), "l"(b))

// ---------------- setup kernels --------------------------------------------
__global__ void zero_kernel() {
    int i = blockIdx.x * blockDim.x + threadIdx.x;
    if (i < N_NODES) { g_deg_out[i] = 0; g_deg_in[i] = 0; g_fill[i] = 0; }
}

__global__ void degree_kernel(const int* __restrict__ src, const int* __restrict__ dst) {
    int e = blockIdx.x * blockDim.x + threadIdx.x;
    if (e < N_EDGES) {
        atomicAdd(&g_deg_out[src[e]], 1);
        atomicAdd(&g_deg_in [dst[e]], 1);
    }
}

// ---- scan phase 1 (+ norm computation folded in) ---------------------------
__global__ void scan1_kernel() {
    __shared__ int warp_sums[32];
    const int b = blockIdx.x, t = threadIdx.x;
    const int lane = t & 31, w = t >> 5;
    const int i = b * SCAN_CHUNK + t;
    int v = 0;
    if (i < N_NODES) {
        v = g_deg_in[i];
        g_norm_dst[i] = rsqrtf(fmaxf((float)v, 1.0f));
        g_norm_src[i] = rsqrtf(fmaxf((float)g_deg_out[i], 1.0f));
    }
    int x = v;
    #pragma unroll
    for (int o = 1; o < 32; o <<= 1) {
        int y = __shfl_up_sync(0xFFFFFFFFu, x, o);
        if (lane >= o) x += y;
    }
    if (lane == 31) warp_sums[w] = x;
    __syncthreads();
    if (t < 32) {
        int s = warp_sums[t];
        #pragma unroll
        for (int o = 1; o < 32; o <<= 1) {
            int y = __shfl_up_sync(0xFFFFFFFFu, s, o);
            if (t >= o) s += y;
        }
        warp_sums[t] = s;
    }
    __syncthreads();
    int incl = x + ((w > 0) ? warp_sums[w - 1] : 0);
    if (i < N_NODES) g_row_ptr[i + 1] = incl;       // chunk-local inclusive
    if (t == SCAN_CHUNK - 1) g_chunk_sum[b] = incl; // chunk total
    if (b == 0 && t == 0) g_row_ptr[0] = 0;
}

// phase 2: one warp, exclusive scan of the 49 chunk totals in place
__global__ void scan2_kernel() {
    const int lane = threadIdx.x;
    int carry = 0;
    for (int base = 0; base < N_CHUNKS; base += 32) {
        int idx = base + lane;
        int v = (idx < N_CHUNKS) ? g_chunk_sum[idx] : 0;
        int x = v;
        #pragma unroll
        for (int o = 1; o < 32; o <<= 1) {
            int y = __shfl_up_sync(0xFFFFFFFFu, x, o);
            if (lane >= o) x += y;
        }
        if (idx < N_CHUNKS) g_chunk_sum[idx] = carry + x - v;  // exclusive
        carry += __shfl_sync(0xFFFFFFFFu, x, 31);
    }
}

// phase 3: add chunk offsets
__global__ void scan3_kernel() {
    int i = blockIdx.x * blockDim.x + threadIdx.x;
    if (i < N_NODES) g_row_ptr[i + 1] += g_chunk_sum[i / SCAN_CHUNK];
}

__global__ void scatter_kernel(const int* __restrict__ src, const int* __restrict__ dst) {
    int e = blockIdx.x * blockDim.x + threadIdx.x;
    if (e < N_EDGES) {
        int d = dst[e];
        int pos = atomicAdd(&g_fill[d], 1);
        g_col[g_row_ptr[d] + pos] = src[e];
    }
}

// ---------------- GEMM1: g_h1 = X @ W1 (no scaling; M=50000,N=128,K=128) ----
// 256 threads, 128-row tile; thread computes 8 rows x 8 cols via f32x2
__global__ void gemm1_kernel(const float* __restrict__ X, const float* __restrict__ W1) {
    extern __shared__ float sm[];
    float* Ws = sm;                  // 128 x 128
    float* Xs = sm + 128 * 128;      // 128 x 132 (padded)
    const int tid = threadIdx.x;
    const int tx = tid & 15, ty = tid >> 4;
    const int row0 = blockIdx.x * 128;

    {   // load W1: 4096 float4 / 256 threads
        const float4* Wg = (const float4*)W1;
        float4* Wsh = (float4*)Ws;
        #pragma unroll
        for (int i = 0; i < 16; i++) Wsh[tid + i * 256] = Wg[tid + i * 256];
    }
    {   // load X tile: 4096 float4
        #pragma unroll
        for (int i = 0; i < 16; i++) {
            int idx = tid + i * 256;
            int r = idx >> 5, c = idx & 31;
            int grow = row0 + r;
            float4 v = make_float4(0.f, 0.f, 0.f, 0.f);
            if (grow < N_NODES) v = ((const float4*)X)[grow * 32 + c];
            *(float4*)(Xs + r * 132 + c * 4) = v;
        }
    }
    __syncthreads();

    unsigned long long acc[8][4];
    #pragma unroll
    for (int r = 0; r < 8; r++)
        #pragma unroll
        for (int c = 0; c < 4; c++) acc[r][c] = 0ull;

    #pragma unroll 2
    for (int k = 0; k < 128; k++) {
        ulonglong2 b01 = *(const ulonglong2*)(Ws + k * 128 + tx * 8);
        ulonglong2 b23 = *(const ulonglong2*)(Ws + k * 128 + tx * 8 + 4);
        unsigned long long b[4] = {b01.x, b01.y, b23.x, b23.y};
        #pragma unroll
        for (int r = 0; r < 8; r++) {
            unsigned long long a = pack_dup(Xs[(ty * 8 + r) * 132 + k]);
            #pragma unroll
            for (int c = 0; c < 4; c++) FMA_F32X2(acc[r][c], a, b[c]);
        }
    }

    #pragma unroll
    for (int r = 0; r < 8; r++) {
        int grow = row0 + ty * 8 + r;
        if (grow < N_NODES) {
            float2 p0 = unpack_f32x2(acc[r][0]);
            float2 p1 = unpack_f32x2(acc[r][1]);
            float2 p2 = unpack_f32x2(acc[r][2]);
            float2 p3 = unpack_f32x2(acc[r][3]);
            float4* out = (float4*)(g_h1 + grow * 128);
            out[tx * 2]     = make_float4(p0.x, p0.y, p1.x, p1.y);
            out[tx * 2 + 1] = make_float4(p2.x, p2.y, p3.x, p3.y);
        }
    }
}

// ---------------- agg1: g_H = relu( (sum ns[s]*h1[s]) * nd + b1 ) -----------
// one warp per dst node, float4 per lane (128 feats); ns applied at gather
__global__ void agg1_kernel(const float* __restrict__ b1) {
    int node = (blockIdx.x * blockDim.x + threadIdx.x) >> 5;
    int lane = threadIdx.x & 31;
    if (node >= N_NODES) return;
    int beg = g_row_ptr[node], end = g_row_ptr[node + 1];
    const float4* h4 = (const float4*)g_h1;
    float4 acc = make_float4(0.f, 0.f, 0.f, 0.f);
    int e = beg;
    for (; e + 4 <= end; e += 4) {
        int s0 = g_col[e], s1 = g_col[e + 1], s2 = g_col[e + 2], s3 = g_col[e + 3];
        float n0 = g_norm_src[s0], n1 = g_norm_src[s1];
        float n2 = g_norm_src[s2], n3 = g_norm_src[s3];
        float4 v0 = h4[s0 * 32 + lane];
        float4 v1 = h4[s1 * 32 + lane];
        float4 v2 = h4[s2 * 32 + lane];
        float4 v3 = h4[s3 * 32 + lane];
        acc.x += fmaf(v0.x, n0, fmaf(v1.x, n1, fmaf(v2.x, n2, v3.x * n3)));
        acc.y += fmaf(v0.y, n0, fmaf(v1.y, n1, fmaf(v2.y, n2, v3.y * n3)));
        acc.z += fmaf(v0.z, n0, fmaf(v1.z, n1, fmaf(v2.z, n2, v3.z * n3)));
        acc.w += fmaf(v0.w, n0, fmaf(v1.w, n1, fmaf(v2.w, n2, v3.w * n3)));
    }
    for (; e < end; e++) {
        int s = g_col[e];
        float ns = g_norm_src[s];
        float4 v = h4[s * 32 + lane];
        acc.x = fmaf(v.x, ns, acc.x);
        acc.y = fmaf(v.y, ns, acc.y);
        acc.z = fmaf(v.z, ns, acc.z);
        acc.w = fmaf(v.w, ns, acc.w);
    }
    float nd = g_norm_dst[node];
    float4 bb = ((const float4*)b1)[lane];
    float4 r;
    r.x = fmaxf(fmaf(acc.x, nd, bb.x), 0.f);
    r.y = fmaxf(fmaf(acc.y, nd, bb.y), 0.f);
    r.z = fmaxf(fmaf(acc.z, nd, bb.z), 0.f);
    r.w = fmaxf(fmaf(acc.w, nd, bb.w), 0.f);
    ((float4*)g_H)[node * 32 + lane] = r;
}

// ---------------- GEMM2: g_h2 = (g_H * norm_src) @ W2 (N=47 padded 48) ------
// 192 threads (16x12), 64-row tile; thread: 4 rows x 4 cols via f32x2
__global__ void gemm2_kernel(const float* __restrict__ W2) {
    extern __shared__ float sm[];
    float* Ws = sm;                 // 128 x 48
    float* Xs = sm + 128 * 48;      // 64 x 132
    const int tid = threadIdx.x;
    const int tx = tid % 12, ty = tid / 12;
    const int row0 = blockIdx.x * 64;

    for (int i = tid; i < 128 * 48; i += 192) {
        int k = i / 48, c = i % 48;
        Ws[i] = (c < NCLS) ? W2[k * NCLS + c] : 0.0f;
    }
    for (int i = tid; i < 64 * 32; i += 192) {
        int r = i >> 5, c = i & 31;
        int grow = row0 + r;
        float4 v = make_float4(0.f, 0.f, 0.f, 0.f);
        if (grow < N_NODES) {
            v = ((const float4*)g_H)[grow * 32 + c];
            float ns = g_norm_src[grow];
            v.x *= ns; v.y *= ns; v.z *= ns; v.w *= ns;
        }
        *(float4*)(Xs + r * 132 + c * 4) = v;
    }
    __syncthreads();

    unsigned long long acc[4][2];
    #pragma unroll
    for (int r = 0; r < 4; r++) { acc[r][0] = 0ull; acc[r][1] = 0ull; }

    #pragma unroll 4
    for (int k = 0; k < 128; k++) {
        ulonglong2 bp = *(const ulonglong2*)(Ws + k * 48 + tx * 4);
        #pragma unroll
        for (int r = 0; r < 4; r++) {
            unsigned long long a = pack_dup(Xs[(ty * 4 + r) * 132 + k]);
            FMA_F32X2(acc[r][0], a, bp.x);
            FMA_F32X2(acc[r][1], a, bp.y);
        }
    }
    #pragma unroll
    for (int r = 0; r < 4; r++) {
        int grow = row0 + ty * 4 + r;
        if (grow < N_NODES) {
            float2 p0 = unpack_f32x2(acc[r][0]);
            float2 p1 = unpack_f32x2(acc[r][1]);
            *(float4*)(g_h2 + grow * NCLS_PAD + tx * 4) =
                make_float4(p0.x, p0.y, p1.x, p1.y);
        }
    }
}

// ---------------- agg2: out = segsum(h2[src]->dst)*nd + b2 (47 feats) -------
__global__ void agg2_kernel(const float* __restrict__ b2, float* __restrict__ out) {
    int node = (blockIdx.x * blockDim.x + threadIdx.x) >> 5;
    int lane = threadIdx.x & 31;
    if (node >= N_NODES) return;
    int beg = g_row_ptr[node], end = g_row_ptr[node + 1];
    bool hi = lane < (NCLS - 32);   // lane+32 < 47
    float a0 = 0.f, a1 = 0.f;
    int e = beg;
    for (; e + 2 <= end; e += 2) {
        int s0 = g_col[e], s1 = g_col[e + 1];
        const float* r0 = g_h2 + s0 * NCLS_PAD;
        const float* r1 = g_h2 + s1 * NCLS_PAD;
        float u0 = r0[lane], u1 = r1[lane];
        float w0 = hi ? r0[lane + 32] : 0.f;
        float w1 = hi ? r1[lane + 32] : 0.f;
        a0 += u0 + u1;
        a1 += w0 + w1;
    }
    for (; e < end; e++) {
        int s = g_col[e];
        const float* r0 = g_h2 + s * NCLS_PAD;
        a0 += r0[lane];
        if (hi) a1 += r0[lane + 32];
    }
    float nd = g_norm_dst[node];
    out[node * NCLS + lane] = fmaf(a0, nd, b2[lane]);
    if (hi) out[node * NCLS + lane + 32] = fmaf(a1, nd, b2[lane + 32]);
}

// ---------------- launch ----------------------------------------------------
extern "C" void kernel_launch(void* const* d_in, const int* in_sizes, int n_in,
                              void* d_out, int out_size) {
    const float* X  = (const float*)d_in[0];
    const int*   ei = (const int*)  d_in[1];
    const float* W1 = (const float*)d_in[2];
    const float* b1 = (const float*)d_in[3];
    const float* W2 = (const float*)d_in[4];
    const float* b2 = (const float*)d_in[5];
    const int* src = ei;
    const int* dst = ei + N_EDGES;
    float* out = (float*)d_out;

    // one-time resources (created on first/correctness call, outside capture)
    static cudaStream_t s_side = nullptr;
    static cudaEvent_t  s_evFork = nullptr, s_evJoin = nullptr;
    if (!s_side) {
        cudaStreamCreateWithFlags(&s_side, cudaStreamNonBlocking);
        cudaEventCreateWithFlags(&s_evFork, cudaEventDisableTiming);
        cudaEventCreateWithFlags(&s_evJoin, cudaEventDisableTiming);
        const int SMEM1 = (128 * 128 + 128 * 132) * (int)sizeof(float);
        const int SMEM2 = (128 * 48  + 64 * 132) * (int)sizeof(float);
        cudaFuncSetAttribute(gemm1_kernel, cudaFuncAttributeMaxDynamicSharedMemorySize, SMEM1);
        cudaFuncSetAttribute(gemm2_kernel, cudaFuncAttributeMaxDynamicSharedMemorySize, SMEM2);
    }
    const int SMEM1 = (128 * 128 + 128 * 132) * (int)sizeof(float);  // 133120
    const int SMEM2 = (128 * 48  + 64 * 132) * (int)sizeof(float);   // 58368

    // fork: gemm1 (X @ W1, no norm dependency) runs on side stream
    cudaEventRecord(s_evFork, 0);
    cudaStreamWaitEvent(s_side, s_evFork, 0);
    gemm1_kernel<<<(N_NODES + 127) / 128, 256, SMEM1, s_side>>>(X, W1);
    cudaEventRecord(s_evJoin, s_side);

    // main chain: CSR build + norms
    zero_kernel   <<<(N_NODES + 255) / 256, 256>>>();
    degree_kernel <<<(N_EDGES + 255) / 256, 256>>>(src, dst);
    scan1_kernel  <<<N_CHUNKS, SCAN_CHUNK>>>();
    scan2_kernel  <<<1, 32>>>();
    scan3_kernel  <<<(N_NODES + 255) / 256, 256>>>();
    scatter_kernel<<<(N_EDGES + 255) / 256, 256>>>(src, dst);

    // join: agg1 needs h1 + CSR + norms
    cudaStreamWaitEvent(0, s_evJoin, 0);
    agg1_kernel   <<<(N_NODES + 7) / 8, 256>>>(b1);
    gemm2_kernel  <<<(N_NODES + 63) / 64, 192, SMEM2>>>(W2);
    agg2_kernel   <<<(N_NODES + 7) / 8, 256>>>(b2, out);
}

// round 4
// speedup vs baseline: 1.3637x; 1.0419x over previous
#include <cuda_runtime.h>
#include <cuda_fp16.h>

#define N_NODES 50000
#define N_EDGES 800000
#define IN_F    128
#define HID     128
#define NCLS    47
#define NCLS_PAD 48

#define SCAN_CHUNK 1024
#define N_CHUNKS ((N_NODES + SCAN_CHUNK - 1) / SCAN_CHUNK)   // 49

// ---------------- scratch (device globals: no allocation allowed) ----------
__device__ int    g_deg_out[N_NODES];
__device__ int    g_deg_in [N_NODES];
__device__ float  g_norm_src[N_NODES];
__device__ float  g_norm_dst[N_NODES];
__device__ int    g_row_ptr[N_NODES + 1];   // [i+1] = chunk-local inclusive scan of deg_in
__device__ int    g_fill  [N_NODES];
__device__ int    g_col   [N_EDGES];
__device__ int    g_chunk_sum[N_CHUNKS];    // exclusive chunk offsets after scan2
__device__ __half g_h1[N_NODES * HID];      // X @ W1, fp16 (UNscaled)
__device__ float  g_h2[N_NODES * NCLS_PAD]; // (H*ns) @ W2 (padded to 48)

// CSR segment bounds from (chunk-local inclusive, exclusive chunk sums)
__device__ __forceinline__ int seg_beg(int i) {
    return g_chunk_sum[i >> 10] + ((i & 1023) ? g_row_ptr[i] : 0);
}
__device__ __forceinline__ int seg_end(int i) {
    return g_chunk_sum[i >> 10] + g_row_ptr[i + 1];
}

// ---------------- f32x2 packed math helpers --------------------------------
__device__ __forceinline__ unsigned long long pack_dup(float x) {
    unsigned long long r;
    unsigned u = __float_as_uint(x);
    asm("mov.b64 %0, {%1, %1};" : "=l"(r) : "r"(u));
    return r;
}
__device__ __forceinline__ float2 unpack_f32x2(unsigned long long p) {
    unsigned lo, hi;
    asm("mov.b64 {%0, %1}, %2;" : "=r"(lo), "=r"(hi) : "l"(p));
    return make_float2(__uint_as_float(lo), __uint_as_float(hi));
}
#define FMA_F32X2(acc, a, b) \
    asm("fma.rn.f32x2 %0, %1, %2, %0;" : "+l"(acc) : "l"(a), "l"(b))

// ---------------- setup kernels --------------------------------------------
__global__ void zero_kernel() {
    int i = blockIdx.x * blockDim.x + threadIdx.x;
    if (i < N_NODES) { g_deg_out[i] = 0; g_deg_in[i] = 0; g_fill[i] = 0; }
}

__global__ void degree_kernel(const int* __restrict__ src, const int* __restrict__ dst) {
    int e = blockIdx.x * blockDim.x + threadIdx.x;
    if (e < N_EDGES) {
        atomicAdd(&g_deg_out[src[e]], 1);
        atomicAdd(&g_deg_in [dst[e]], 1);
    }
}

// scan phase 1: per-chunk inclusive scan of deg_in + norms folded in
__global__ void scan1_kernel() {
    __shared__ int warp_sums[32];
    const int b = blockIdx.x, t = threadIdx.x;
    const int lane = t & 31, w = t >> 5;
    const int i = b * SCAN_CHUNK + t;
    int v = 0;
    if (i < N_NODES) {
        v = g_deg_in[i];
        g_norm_dst[i] = rsqrtf(fmaxf((float)v, 1.0f));
        g_norm_src[i] = rsqrtf(fmaxf((float)g_deg_out[i], 1.0f));
    }
    int x = v;
    #pragma unroll
    for (int o = 1; o < 32; o <<= 1) {
        int y = __shfl_up_sync(0xFFFFFFFFu, x, o);
        if (lane >= o) x += y;
    }
    if (lane == 31) warp_sums[w] = x;
    __syncthreads();
    if (t < 32) {
        int s = warp_sums[t];
        #pragma unroll
        for (int o = 1; o < 32; o <<= 1) {
            int y = __shfl_up_sync(0xFFFFFFFFu, s, o);
            if (t >= o) s += y;
        }
        warp_sums[t] = s;
    }
    __syncthreads();
    int incl = x + ((w > 0) ? warp_sums[w - 1] : 0);
    if (i < N_NODES) g_row_ptr[i + 1] = incl;       // chunk-local inclusive
    if (t == SCAN_CHUNK - 1) g_chunk_sum[b] = incl; // chunk total
}

// scan phase 2: one warp, exclusive scan of the 49 chunk totals in place
__global__ void scan2_kernel() {
    const int lane = threadIdx.x;
    int carry = 0;
    for (int base = 0; base < N_CHUNKS; base += 32) {
        int idx = base + lane;
        int v = (idx < N_CHUNKS) ? g_chunk_sum[idx] : 0;
        int x = v;
        #pragma unroll
        for (int o = 1; o < 32; o <<= 1) {
            int y = __shfl_up_sync(0xFFFFFFFFu, x, o);
            if (lane >= o) x += y;
        }
        if (idx < N_CHUNKS) g_chunk_sum[idx] = carry + x - v;  // exclusive
        carry += __shfl_sync(0xFFFFFFFFu, x, 31);
    }
}

__global__ void scatter_kernel(const int* __restrict__ src, const int* __restrict__ dst) {
    int e = blockIdx.x * blockDim.x + threadIdx.x;
    if (e < N_EDGES) {
        int d = dst[e];
        int base = seg_beg(d);
        int pos = atomicAdd(&g_fill[d], 1);
        g_col[base + pos] = src[e];
    }
}

// ---------------- GEMM1: g_h1 = fp16(X @ W1)  (M=50000,N=128,K=128) --------
// 256 threads, 128-row tile; thread computes 8 rows x 8 cols via f32x2
__global__ void gemm1_kernel(const float* __restrict__ X, const float* __restrict__ W1) {
    extern __shared__ float sm[];
    float* Ws = sm;                  // 128 x 128
    float* Xs = sm + 128 * 128;      // 128 x 132 (padded)
    const int tid = threadIdx.x;
    const int tx = tid & 15, ty = tid >> 4;
    const int row0 = blockIdx.x * 128;

    {   // load W1: 4096 float4 / 256 threads
        const float4* Wg = (const float4*)W1;
        float4* Wsh = (float4*)Ws;
        #pragma unroll
        for (int i = 0; i < 16; i++) Wsh[tid + i * 256] = Wg[tid + i * 256];
    }
    {   // load X tile: 4096 float4
        #pragma unroll
        for (int i = 0; i < 16; i++) {
            int idx = tid + i * 256;
            int r = idx >> 5, c = idx & 31;
            int grow = row0 + r;
            float4 v = make_float4(0.f, 0.f, 0.f, 0.f);
            if (grow < N_NODES) v = ((const float4*)X)[grow * 32 + c];
            *(float4*)(Xs + r * 132 + c * 4) = v;
        }
    }
    __syncthreads();

    unsigned long long acc[8][4];
    #pragma unroll
    for (int r = 0; r < 8; r++)
        #pragma unroll
        for (int c = 0; c < 4; c++) acc[r][c] = 0ull;

    #pragma unroll 2
    for (int k = 0; k < 128; k++) {
        ulonglong2 b01 = *(const ulonglong2*)(Ws + k * 128 + tx * 8);
        ulonglong2 b23 = *(const ulonglong2*)(Ws + k * 128 + tx * 8 + 4);
        unsigned long long b[4] = {b01.x, b01.y, b23.x, b23.y};
        #pragma unroll
        for (int r = 0; r < 8; r++) {
            unsigned long long a = pack_dup(Xs[(ty * 8 + r) * 132 + k]);
            #pragma unroll
            for (int c = 0; c < 4; c++) FMA_F32X2(acc[r][c], a, b[c]);
        }
    }

    #pragma unroll
    for (int r = 0; r < 8; r++) {
        int grow = row0 + ty * 8 + r;
        if (grow < N_NODES) {
            float2 p0 = unpack_f32x2(acc[r][0]);
            float2 p1 = unpack_f32x2(acc[r][1]);
            float2 p2 = unpack_f32x2(acc[r][2]);
            float2 p3 = unpack_f32x2(acc[r][3]);
            __half2 h0 = __floats2half2_rn(p0.x, p0.y);
            __half2 h1 = __floats2half2_rn(p1.x, p1.y);
            __half2 h2 = __floats2half2_rn(p2.x, p2.y);
            __half2 h3 = __floats2half2_rn(p3.x, p3.y);
            // 8 halves = 16B per thread -> one uint4 store; row = 16 uint4
            uint4 pk;
            pk.x = *(unsigned*)&h0; pk.y = *(unsigned*)&h1;
            pk.z = *(unsigned*)&h2; pk.w = *(unsigned*)&h3;
            ((uint4*)g_h1)[grow * 16 + tx] = pk;
        }
    }
}

// ---------------- layer2: fused agg1 + gemm2 --------------------------------
// Block = 256 thr handles 64 nodes.
// Phase A: 8 warps gather fp16 h1 rows over CSR, epilogue
//          Hs = relu(acc*nd + b1) * ns  into smem (64 x 132).
// Phase B: gemm2 mainloop (192 active threads) -> g_h2 (48-padded).
__global__ void layer2_kernel(const float* __restrict__ W2, const float* __restrict__ b1) {
    extern __shared__ float sm[];
    float* Ws = sm;                 // 128 x 48
    float* Hs = sm + 128 * 48;      // 64 x 132 (padded)
    const int tid = threadIdx.x;
    const int lane = tid & 31, w = tid >> 5;
    const int row0 = blockIdx.x * 64;

    // load W2 padded to 48 cols
    for (int i = tid; i < 128 * 48; i += 256) {
        int k = i / 48, c = i % 48;
        Ws[i] = (c < NCLS) ? W2[k * NCLS + c] : 0.0f;
    }

    // Phase A: warp w handles local rows {w + 8j}
    const uint2* h1p = (const uint2*)g_h1;   // 4 halves per uint2; row = 32 uint2
    float b1v0 = b1[lane * 4 + 0], b1v1 = b1[lane * 4 + 1];
    float b1v2 = b1[lane * 4 + 2], b1v3 = b1[lane * 4 + 3];
    #pragma unroll
    for (int j = 0; j < 8; j++) {
        int r = w + j * 8;
        int node = row0 + r;
        float4 acc = make_float4(0.f, 0.f, 0.f, 0.f);
        if (node < N_NODES) {
            int beg = seg_beg(node), end = seg_end(node);
            int e = beg;
            for (; e + 4 <= end; e += 4) {
                int s0 = g_col[e],     s1 = g_col[e + 1];
                int s2 = g_col[e + 2], s3 = g_col[e + 3];
                float n0 = g_norm_src[s0], n1 = g_norm_src[s1];
                float n2 = g_norm_src[s2], n3 = g_norm_src[s3];
                uint2 u0 = h1p[s0 * 32 + lane];
                uint2 u1 = h1p[s1 * 32 + lane];
                uint2 u2 = h1p[s2 * 32 + lane];
                uint2 u3 = h1p[s3 * 32 + lane];
                float2 a0 = __half22float2(*(__half2*)&u0.x), c0 = __half22float2(*(__half2*)&u0.y);
                float2 a1 = __half22float2(*(__half2*)&u1.x), c1 = __half22float2(*(__half2*)&u1.y);
                float2 a2 = __half22float2(*(__half2*)&u2.x), c2 = __half22float2(*(__half2*)&u2.y);
                float2 a3 = __half22float2(*(__half2*)&u3.x), c3 = __half22float2(*(__half2*)&u3.y);
                acc.x += fmaf(a0.x, n0, fmaf(a1.x, n1, fmaf(a2.x, n2, a3.x * n3)));
                acc.y += fmaf(a0.y, n0, fmaf(a1.y, n1, fmaf(a2.y, n2, a3.y * n3)));
                acc.z += fmaf(c0.x, n0, fmaf(c1.x, n1, fmaf(c2.x, n2, c3.x * n3)));
                acc.w += fmaf(c0.y, n0, fmaf(c1.y, n1, fmaf(c2.y, n2, c3.y * n3)));
            }
            for (; e < end; e++) {
                int s = g_col[e];
                float ns = g_norm_src[s];
                uint2 u = h1p[s * 32 + lane];
                float2 a = __half22float2(*(__half2*)&u.x);
                float2 c = __half22float2(*(__half2*)&u.y);
                acc.x = fmaf(a.x, ns, acc.x);
                acc.y = fmaf(a.y, ns, acc.y);
                acc.z = fmaf(c.x, ns, acc.z);
                acc.w = fmaf(c.y, ns, acc.w);
            }
            float nd = g_norm_dst[node];
            float ns_o = g_norm_src[node];   // next layer's row scaling
            float4 hv;
            hv.x = fmaxf(fmaf(acc.x, nd, b1v0), 0.f) * ns_o;
            hv.y = fmaxf(fmaf(acc.y, nd, b1v1), 0.f) * ns_o;
            hv.z = fmaxf(fmaf(acc.z, nd, b1v2), 0.f) * ns_o;
            hv.w = fmaxf(fmaf(acc.w, nd, b1v3), 0.f) * ns_o;
            *(float4*)(Hs + r * 132 + lane * 4) = hv;
        } else {
            *(float4*)(Hs + r * 132 + lane * 4) = make_float4(0.f, 0.f, 0.f, 0.f);
        }
    }
    __syncthreads();

    // Phase B: gemm2, 192 active threads (16 x 12)
    if (tid < 192) {
        const int tx = tid % 12, ty = tid / 12;
        unsigned long long acc[4][2];
        #pragma unroll
        for (int r = 0; r < 4; r++) { acc[r][0] = 0ull; acc[r][1] = 0ull; }

        #pragma unroll 4
        for (int k = 0; k < 128; k++) {
            ulonglong2 bp = *(const ulonglong2*)(Ws + k * 48 + tx * 4);
            #pragma unroll
            for (int r = 0; r < 4; r++) {
                unsigned long long a = pack_dup(Hs[(ty * 4 + r) * 132 + k]);
                FMA_F32X2(acc[r][0], a, bp.x);
                FMA_F32X2(acc[r][1], a, bp.y);
            }
        }
        #pragma unroll
        for (int r = 0; r < 4; r++) {
            int grow = row0 + ty * 4 + r;
            if (grow < N_NODES) {
                float2 p0 = unpack_f32x2(acc[r][0]);
                float2 p1 = unpack_f32x2(acc[r][1]);
                *(float4*)(g_h2 + grow * NCLS_PAD + tx * 4) =
                    make_float4(p0.x, p0.y, p1.x, p1.y);
            }
        }
    }
}

// ---------------- agg2: out = segsum(h2[src]->dst)*nd + b2 (47 feats) -------
__global__ void agg2_kernel(const float* __restrict__ b2, float* __restrict__ out) {
    int node = (blockIdx.x * blockDim.x + threadIdx.x) >> 5;
    int lane = threadIdx.x & 31;
    if (node >= N_NODES) return;
    int beg = seg_beg(node), end = seg_end(node);
    bool hi = lane < (NCLS - 32);   // lane+32 < 47
    float a0 = 0.f, a1 = 0.f;
    int e = beg;
    for (; e + 2 <= end; e += 2) {
        int s0 = g_col[e], s1 = g_col[e + 1];
        const float* r0 = g_h2 + s0 * NCLS_PAD;
        const float* r1 = g_h2 + s1 * NCLS_PAD;
        float u0 = r0[lane], u1 = r1[lane];
        float w0 = hi ? r0[lane + 32] : 0.f;
        float w1 = hi ? r1[lane + 32] : 0.f;
        a0 += u0 + u1;
        a1 += w0 + w1;
    }
    for (; e < end; e++) {
        int s = g_col[e];
        const float* r0 = g_h2 + s * NCLS_PAD;
        a0 += r0[lane];
        if (hi) a1 += r0[lane + 32];
    }
    float nd = g_norm_dst[node];
    out[node * NCLS + lane] = fmaf(a0, nd, b2[lane]);
    if (hi) out[node * NCLS + lane + 32] = fmaf(a1, nd, b2[lane + 32]);
}

// ---------------- launch ----------------------------------------------------
extern "C" void kernel_launch(void* const* d_in, const int* in_sizes, int n_in,
                              void* d_out, int out_size) {
    const float* X  = (const float*)d_in[0];
    const int*   ei = (const int*)  d_in[1];
    const float* W1 = (const float*)d_in[2];
    const float* b1 = (const float*)d_in[3];
    const float* W2 = (const float*)d_in[4];
    const float* b2 = (const float*)d_in[5];
    const int* src = ei;
    const int* dst = ei + N_EDGES;
    float* out = (float*)d_out;

    const int SMEM1 = (128 * 128 + 128 * 132) * (int)sizeof(float);  // 133120
    const int SMEM2 = (128 * 48  + 64 * 132) * (int)sizeof(float);   // 58368

    static cudaStream_t s_side = nullptr;
    static cudaEvent_t  s_evFork = nullptr, s_evJoin = nullptr;
    if (!s_side) {
        cudaStreamCreateWithFlags(&s_side, cudaStreamNonBlocking);
        cudaEventCreateWithFlags(&s_evFork, cudaEventDisableTiming);
        cudaEventCreateWithFlags(&s_evJoin, cudaEventDisableTiming);
        cudaFuncSetAttribute(gemm1_kernel,  cudaFuncAttributeMaxDynamicSharedMemorySize, SMEM1);
        cudaFuncSetAttribute(layer2_kernel, cudaFuncAttributeMaxDynamicSharedMemorySize, SMEM2);
    }

    // fork: gemm1 (X @ W1, norm-independent) on side stream
    cudaEventRecord(s_evFork, 0);
    cudaStreamWaitEvent(s_side, s_evFork, 0);
    gemm1_kernel<<<(N_NODES + 127) / 128, 256, SMEM1, s_side>>>(X, W1);
    cudaEventRecord(s_evJoin, s_side);

    // main chain: CSR build + norms
    zero_kernel   <<<(N_NODES + 255) / 256, 256>>>();
    degree_kernel <<<(N_EDGES + 255) / 256, 256>>>(src, dst);
    scan1_kernel  <<<N_CHUNKS, SCAN_CHUNK>>>();
    scan2_kernel  <<<1, 32>>>();
    scatter_kernel<<<(N_EDGES + 255) / 256, 256>>>(src, dst);

    // join: layer2 needs h1 + CSR + norms
    cudaStreamWaitEvent(0, s_evJoin, 0);
    layer2_kernel <<<(N_NODES + 63) / 64, 256, SMEM2>>>(W2, b1);
    agg2_kernel   <<<(N_NODES + 7) / 8, 256>>>(b2, out);
}

// round 5
// speedup vs baseline: 1.4798x; 1.0851x over previous
#include <cuda_runtime.h>
#include <cuda_fp16.h>

#define N_NODES 50000
#define N_EDGES 800000
#define IN_F    128
#define HID     128
#define NCLS    47
#define NCLS_PAD 48

#define SCAN_CHUNK 1024
#define N_CHUNKS ((N_NODES + SCAN_CHUNK - 1) / SCAN_CHUNK)   // 49

// ---------------- scratch (device globals: zero-init at load) ---------------
// Invariant: every kernel_launch execution leaves g_deg_*, g_fill, g_scan_ctr
// zeroed (agg2 tail + scan1 last block), so each run starts clean.
__device__ int    g_deg_out[N_NODES];
__device__ int    g_deg_in [N_NODES];
__device__ float  g_norm_src[N_NODES];
__device__ float  g_norm_dst[N_NODES];
__device__ int    g_row_ptr[N_NODES + 1];   // [i+1] = chunk-local inclusive scan
__device__ int    g_fill  [N_NODES];
__device__ int    g_col   [N_EDGES];
__device__ int    g_chunk_sum[N_CHUNKS];    // exclusive chunk offsets after scan1
__device__ int    g_scan_ctr;
__device__ __half g_h1[N_NODES * HID];      // X @ W1, fp16 (UNscaled)
__device__ __half g_h2[N_NODES * NCLS_PAD]; // (H*ns) @ W2, fp16 (48-padded)

// CSR segment bounds from (chunk-local inclusive, exclusive chunk sums)
__device__ __forceinline__ int seg_beg(int i) {
    return g_chunk_sum[i >> 10] + ((i & 1023) ? g_row_ptr[i] : 0);
}
__device__ __forceinline__ int seg_end(int i) {
    return g_chunk_sum[i >> 10] + g_row_ptr[i + 1];
}

// ---------------- f32x2 packed math helpers --------------------------------
__device__ __forceinline__ unsigned long long pack_dup(float x) {
    unsigned long long r;
    unsigned u = __float_as_uint(x);
    asm("mov.b64 %0, {%1, %1};" : "=l"(r) : "r"(u));
    return r;
}
__device__ __forceinline__ float2 unpack_f32x2(unsigned long long p) {
    unsigned lo, hi;
    asm("mov.b64 {%0, %1}, %2;" : "=r"(lo), "=r"(hi) : "l"(p));
    return make_float2(__uint_as_float(lo), __uint_as_float(hi));
}
#define FMA_F32X2(acc, a, b) \
    asm("fma.rn.f32x2 %0, %1, %2, %0;" : "+l"(acc) : "l"(a), "l"(b))

// ---------------- degree ----------------------------------------------------
__global__ void degree_kernel(const int* __restrict__ src, const int* __restrict__ dst) {
    int e = blockIdx.x * blockDim.x + threadIdx.x;
    if (e < N_EDGES) {
        atomicAdd(&g_deg_out[src[e]], 1);
        atomicAdd(&g_deg_in [dst[e]], 1);
    }
}

// ---- scan: per-chunk inclusive scan + norms; LAST block scans chunk sums ---
__global__ void scan_kernel() {
    __shared__ int warp_sums[32];
    __shared__ int is_last;
    const int b = blockIdx.x, t = threadIdx.x;
    const int lane = t & 31, w = t >> 5;
    const int i = b * SCAN_CHUNK + t;
    int v = 0;
    if (i < N_NODES) {
        v = g_deg_in[i];
        g_norm_dst[i] = rsqrtf(fmaxf((float)v, 1.0f));
        g_norm_src[i] = rsqrtf(fmaxf((float)g_deg_out[i], 1.0f));
    }
    int x = v;
    #pragma unroll
    for (int o = 1; o < 32; o <<= 1) {
        int y = __shfl_up_sync(0xFFFFFFFFu, x, o);
        if (lane >= o) x += y;
    }
    if (lane == 31) warp_sums[w] = x;
    __syncthreads();
    if (t < 32) {
        int s = warp_sums[t];
        #pragma unroll
        for (int o = 1; o < 32; o <<= 1) {
            int y = __shfl_up_sync(0xFFFFFFFFu, s, o);
            if (t >= o) s += y;
        }
        warp_sums[t] = s;
    }
    __syncthreads();
    int incl = x + ((w > 0) ? warp_sums[w - 1] : 0);
    if (i < N_NODES) g_row_ptr[i + 1] = incl;       // chunk-local inclusive
    if (t == SCAN_CHUNK - 1) g_chunk_sum[b] = incl; // chunk total

    // last-block: exclusive scan of the N_CHUNKS chunk totals
    __threadfence();
    if (t == 0) is_last = (atomicAdd(&g_scan_ctr, 1) == N_CHUNKS - 1) ? 1 : 0;
    __syncthreads();
    if (is_last && t < 32) {
        volatile int* cs = (volatile int*)g_chunk_sum;
        int carry = 0;
        for (int base = 0; base < N_CHUNKS; base += 32) {
            int idx = base + t;
            int vv = (idx < N_CHUNKS) ? cs[idx] : 0;
            int xx = vv;
            #pragma unroll
            for (int o = 1; o < 32; o <<= 1) {
                int y = __shfl_up_sync(0xFFFFFFFFu, xx, o);
                if (t >= o) xx += y;
            }
            if (idx < N_CHUNKS) g_chunk_sum[idx] = carry + xx - vv;  // exclusive
            carry += __shfl_sync(0xFFFFFFFFu, xx, 31);
        }
        if (t == 0) g_scan_ctr = 0;   // self-clean for next run
    }
}

__global__ void scatter_kernel(const int* __restrict__ src, const int* __restrict__ dst) {
    int e = blockIdx.x * blockDim.x + threadIdx.x;
    if (e < N_EDGES) {
        int d = dst[e];
        int base = seg_beg(d);
        int pos = atomicAdd(&g_fill[d], 1);
        g_col[base + pos] = src[e];
    }
}

// ---------------- GEMM1: g_h1 = fp16(X @ W1)  (M=50000,N=128,K=128) --------
// 256 threads, 128-row tile; thread computes 8 rows x 8 cols via f32x2;
// A-operand loaded as float4 over k (4x fewer LDS).
__global__ void gemm1_kernel(const float* __restrict__ X, const float* __restrict__ W1) {
    extern __shared__ float sm[];
    float* Ws = sm;                  // 128 x 128
    float* Xs = sm + 128 * 128;      // 128 x 132 (padded)
    const int tid = threadIdx.x;
    const int tx = tid & 15, ty = tid >> 4;
    const int row0 = blockIdx.x * 128;

    {   // load W1: 4096 float4 / 256 threads
        const float4* Wg = (const float4*)W1;
        float4* Wsh = (float4*)Ws;
        #pragma unroll
        for (int i = 0; i < 16; i++) Wsh[tid + i * 256] = Wg[tid + i * 256];
    }
    {   // load X tile: 4096 float4
        #pragma unroll
        for (int i = 0; i < 16; i++) {
            int idx = tid + i * 256;
            int r = idx >> 5, c = idx & 31;
            int grow = row0 + r;
            float4 v = make_float4(0.f, 0.f, 0.f, 0.f);
            if (grow < N_NODES) v = ((const float4*)X)[grow * 32 + c];
            *(float4*)(Xs + r * 132 + c * 4) = v;
        }
    }
    __syncthreads();

    unsigned long long acc[8][4];
    #pragma unroll
    for (int r = 0; r < 8; r++)
        #pragma unroll
        for (int c = 0; c < 4; c++) acc[r][c] = 0ull;

    for (int k4 = 0; k4 < 128; k4 += 4) {
        float4 a4[8];
        #pragma unroll
        for (int r = 0; r < 8; r++)
            a4[r] = *(const float4*)(Xs + (ty * 8 + r) * 132 + k4);
        #pragma unroll
        for (int kk = 0; kk < 4; kk++) {
            ulonglong2 b01 = *(const ulonglong2*)(Ws + (k4 + kk) * 128 + tx * 8);
            ulonglong2 b23 = *(const ulonglong2*)(Ws + (k4 + kk) * 128 + tx * 8 + 4);
            #pragma unroll
            for (int r = 0; r < 8; r++) {
                float af = (kk == 0) ? a4[r].x : (kk == 1) ? a4[r].y
                         : (kk == 2) ? a4[r].z : a4[r].w;
                unsigned long long a = pack_dup(af);
                FMA_F32X2(acc[r][0], a, b01.x);
                FMA_F32X2(acc[r][1], a, b01.y);
                FMA_F32X2(acc[r][2], a, b23.x);
                FMA_F32X2(acc[r][3], a, b23.y);
            }
        }
    }

    #pragma unroll
    for (int r = 0; r < 8; r++) {
        int grow = row0 + ty * 8 + r;
        if (grow < N_NODES) {
            float2 p0 = unpack_f32x2(acc[r][0]);
            float2 p1 = unpack_f32x2(acc[r][1]);
            float2 p2 = unpack_f32x2(acc[r][2]);
            float2 p3 = unpack_f32x2(acc[r][3]);
            __half2 h0 = __floats2half2_rn(p0.x, p0.y);
            __half2 h1 = __floats2half2_rn(p1.x, p1.y);
            __half2 h2 = __floats2half2_rn(p2.x, p2.y);
            __half2 h3 = __floats2half2_rn(p3.x, p3.y);
            uint4 pk;
            pk.x = *(unsigned*)&h0; pk.y = *(unsigned*)&h1;
            pk.z = *(unsigned*)&h2; pk.w = *(unsigned*)&h3;
            ((uint4*)g_h1)[grow * 16 + tx] = pk;
        }
    }
}

// ---------------- layer2: fused agg1 + gemm2 --------------------------------
__global__ void layer2_kernel(const float* __restrict__ W2, const float* __restrict__ b1) {
    extern __shared__ float sm[];
    float* Ws = sm;                 // 128 x 48
    float* Hs = sm + 128 * 48;      // 64 x 132 (padded)
    const int tid = threadIdx.x;
    const int lane = tid & 31, w = tid >> 5;
    const int row0 = blockIdx.x * 64;

    for (int i = tid; i < 128 * 48; i += 256) {
        int k = i / 48, c = i % 48;
        Ws[i] = (c < NCLS) ? W2[k * NCLS + c] : 0.0f;
    }

    // Phase A: warp w gathers local rows {w + 8j}
    const uint2* h1p = (const uint2*)g_h1;   // 4 halves per uint2; row = 32 uint2
    float b1v0 = b1[lane * 4 + 0], b1v1 = b1[lane * 4 + 1];
    float b1v2 = b1[lane * 4 + 2], b1v3 = b1[lane * 4 + 3];
    #pragma unroll
    for (int j = 0; j < 8; j++) {
        int r = w + j * 8;
        int node = row0 + r;
        float4 acc = make_float4(0.f, 0.f, 0.f, 0.f);
        if (node < N_NODES) {
            int beg = seg_beg(node), end = seg_end(node);
            int e = beg;
            for (; e + 4 <= end; e += 4) {
                int s0 = g_col[e],     s1 = g_col[e + 1];
                int s2 = g_col[e + 2], s3 = g_col[e + 3];
                float n0 = g_norm_src[s0], n1 = g_norm_src[s1];
                float n2 = g_norm_src[s2], n3 = g_norm_src[s3];
                uint2 u0 = h1p[s0 * 32 + lane];
                uint2 u1 = h1p[s1 * 32 + lane];
                uint2 u2 = h1p[s2 * 32 + lane];
                uint2 u3 = h1p[s3 * 32 + lane];
                float2 a0 = __half22float2(*(__half2*)&u0.x), c0 = __half22float2(*(__half2*)&u0.y);
                float2 a1 = __half22float2(*(__half2*)&u1.x), c1 = __half22float2(*(__half2*)&u1.y);
                float2 a2 = __half22float2(*(__half2*)&u2.x), c2 = __half22float2(*(__half2*)&u2.y);
                float2 a3 = __half22float2(*(__half2*)&u3.x), c3 = __half22float2(*(__half2*)&u3.y);
                acc.x += fmaf(a0.x, n0, fmaf(a1.x, n1, fmaf(a2.x, n2, a3.x * n3)));
                acc.y += fmaf(a0.y, n0, fmaf(a1.y, n1, fmaf(a2.y, n2, a3.y * n3)));
                acc.z += fmaf(c0.x, n0, fmaf(c1.x, n1, fmaf(c2.x, n2, c3.x * n3)));
                acc.w += fmaf(c0.y, n0, fmaf(c1.y, n1, fmaf(c2.y, n2, c3.y * n3)));
            }
            for (; e < end; e++) {
                int s = g_col[e];
                float ns = g_norm_src[s];
                uint2 u = h1p[s * 32 + lane];
                float2 a = __half22float2(*(__half2*)&u.x);
                float2 c = __half22float2(*(__half2*)&u.y);
                acc.x = fmaf(a.x, ns, acc.x);
                acc.y = fmaf(a.y, ns, acc.y);
                acc.z = fmaf(c.x, ns, acc.z);
                acc.w = fmaf(c.y, ns, acc.w);
            }
            float nd = g_norm_dst[node];
            float ns_o = g_norm_src[node];   // next layer's row scaling
            float4 hv;
            hv.x = fmaxf(fmaf(acc.x, nd, b1v0), 0.f) * ns_o;
            hv.y = fmaxf(fmaf(acc.y, nd, b1v1), 0.f) * ns_o;
            hv.z = fmaxf(fmaf(acc.z, nd, b1v2), 0.f) * ns_o;
            hv.w = fmaxf(fmaf(acc.w, nd, b1v3), 0.f) * ns_o;
            *(float4*)(Hs + r * 132 + lane * 4) = hv;
        } else {
            *(float4*)(Hs + r * 132 + lane * 4) = make_float4(0.f, 0.f, 0.f, 0.f);
        }
    }
    __syncthreads();

    // Phase B: gemm2, 192 active threads (16 x 12), vectorized A loads
    if (tid < 192) {
        const int tx = tid % 12, ty = tid / 12;
        unsigned long long acc[4][2];
        #pragma unroll
        for (int r = 0; r < 4; r++) { acc[r][0] = 0ull; acc[r][1] = 0ull; }

        for (int k4 = 0; k4 < 128; k4 += 4) {
            float4 a4[4];
            #pragma unroll
            for (int r = 0; r < 4; r++)
                a4[r] = *(const float4*)(Hs + (ty * 4 + r) * 132 + k4);
            #pragma unroll
            for (int kk = 0; kk < 4; kk++) {
                ulonglong2 bp = *(const ulonglong2*)(Ws + (k4 + kk) * 48 + tx * 4);
                #pragma unroll
                for (int r = 0; r < 4; r++) {
                    float af = (kk == 0) ? a4[r].x : (kk == 1) ? a4[r].y
                             : (kk == 2) ? a4[r].z : a4[r].w;
                    unsigned long long a = pack_dup(af);
                    FMA_F32X2(acc[r][0], a, bp.x);
                    FMA_F32X2(acc[r][1], a, bp.y);
                }
            }
        }
        #pragma unroll
        for (int r = 0; r < 4; r++) {
            int grow = row0 + ty * 4 + r;
            if (grow < N_NODES) {
                float2 p0 = unpack_f32x2(acc[r][0]);
                float2 p1 = unpack_f32x2(acc[r][1]);
                __half2 q0 = __floats2half2_rn(p0.x, p0.y);
                __half2 q1 = __floats2half2_rn(p1.x, p1.y);
                uint2 pk;
                pk.x = *(unsigned*)&q0; pk.y = *(unsigned*)&q1;
                *(uint2*)(g_h2 + grow * NCLS_PAD + tx * 4) = pk;
            }
        }
    }
}

// ---------------- agg2: out = segsum(h2[src]->dst)*nd + b2 (47 feats) -------
// one warp per node; 24 active lanes, half2 per lane (classes 2l, 2l+1)
__global__ void agg2_kernel(const float* __restrict__ b2, float* __restrict__ out) {
    int node = (blockIdx.x * blockDim.x + threadIdx.x) >> 5;
    int lane = threadIdx.x & 31;
    if (node >= N_NODES) return;
    int beg = seg_beg(node), end = seg_end(node);
    if (lane < 24) {
        float a0 = 0.f, a1 = 0.f;
        const __half2* base = (const __half2*)g_h2;
        int e = beg;
        for (; e + 4 <= end; e += 4) {
            int s0 = g_col[e],     s1 = g_col[e + 1];
            int s2 = g_col[e + 2], s3 = g_col[e + 3];
            float2 f0 = __half22float2(base[s0 * 24 + lane]);
            float2 f1 = __half22float2(base[s1 * 24 + lane]);
            float2 f2 = __half22float2(base[s2 * 24 + lane]);
            float2 f3 = __half22float2(base[s3 * 24 + lane]);
            a0 += (f0.x + f1.x) + (f2.x + f3.x);
            a1 += (f0.y + f1.y) + (f2.y + f3.y);
        }
        for (; e < end; e++) {
            int s = g_col[e];
            float2 f = __half22float2(base[s * 24 + lane]);
            a0 += f.x; a1 += f.y;
        }
        float nd = g_norm_dst[node];
        int c = lane * 2;
        out[node * NCLS + c] = fmaf(a0, nd, b2[c]);
        if (c + 1 < NCLS) out[node * NCLS + c + 1] = fmaf(a1, nd, b2[c + 1]);
    }
    // self-clean scratch for next run (zero-init invariant)
    if (lane == 24) { g_deg_in[node] = 0; g_deg_out[node] = 0; g_fill[node] = 0; }
}

// ---------------- launch ----------------------------------------------------
extern "C" void kernel_launch(void* const* d_in, const int* in_sizes, int n_in,
                              void* d_out, int out_size) {
    const float* X  = (const float*)d_in[0];
    const int*   ei = (const int*)  d_in[1];
    const float* W1 = (const float*)d_in[2];
    const float* b1 = (const float*)d_in[3];
    const float* W2 = (const float*)d_in[4];
    const float* b2 = (const float*)d_in[5];
    const int* src = ei;
    const int* dst = ei + N_EDGES;
    float* out = (float*)d_out;

    const int SMEM1 = (128 * 128 + 128 * 132) * (int)sizeof(float);  // 133120
    const int SMEM2 = (128 * 48  + 64 * 132) * (int)sizeof(float);   // 58368

    static cudaStream_t s_side = nullptr;
    static cudaEvent_t  s_evFork = nullptr, s_evJoin = nullptr;
    if (!s_side) {
        cudaStreamCreateWithFlags(&s_side, cudaStreamNonBlocking);
        cudaEventCreateWithFlags(&s_evFork, cudaEventDisableTiming);
        cudaEventCreateWithFlags(&s_evJoin, cudaEventDisableTiming);
        cudaFuncSetAttribute(gemm1_kernel,  cudaFuncAttributeMaxDynamicSharedMemorySize, SMEM1);
        cudaFuncSetAttribute(layer2_kernel, cudaFuncAttributeMaxDynamicSharedMemorySize, SMEM2);
    }

    // fork: gemm1 (X @ W1, norm-independent) on side stream
    cudaEventRecord(s_evFork, 0);
    cudaStreamWaitEvent(s_side, s_evFork, 0);
    gemm1_kernel<<<(N_NODES + 127) / 128, 256, SMEM1, s_side>>>(X, W1);
    cudaEventRecord(s_evJoin, s_side);

    // main chain: CSR build + norms (deg/fill arrive zeroed — see invariant)
    degree_kernel <<<(N_EDGES + 255) / 256, 256>>>(src, dst);
    scan_kernel   <<<N_CHUNKS, SCAN_CHUNK>>>();
    scatter_kernel<<<(N_EDGES + 255) / 256, 256>>>(src, dst);

    // join: layer2 needs h1 + CSR + norms
    cudaStreamWaitEvent(0, s_evJoin, 0);
    layer2_kernel <<<(N_NODES + 63) / 64, 256, SMEM2>>>(W2, b1);
    agg2_kernel   <<<(N_NODES + 7) / 8, 256>>>(b2, out);
}